// round 9
// baseline (speedup 1.0000x reference)
#include <cuda_runtime.h>
#include <cstddef>
#include <cstdint>

#define NND 100000
#define EE  1600000
#define RR  8
#define BB  4
#define DD  64

#define LBLK 256                 // threads per layer block
#define NODES_PB 64              // dst nodes per layer block
#define NLB ((NND + NODES_PB - 1) / NODES_PB)   // 1563
#define NCH ((NND + 1023) / 1024)               // 98 scan chunks

typedef unsigned long long ull;
typedef unsigned int uint;

// Scratch (no runtime allocation allowed) ------------------------------------
__device__ float g_h1[(size_t)NND * DD];
__device__ float g_h2[(size_t)NND * DD];
__device__ int   g_deg[NND];
__device__ int   g_rowptr[NND + 1];
__device__ int   g_cur[NND];
__device__ ull   g_partial[NCH];  // lookback: (ready<<32)|chunk_sum
__device__ ull   g_edata[EE];     // (norm bits << 32) | (ety << 20) | src

// ---------------------------------------------------------------- f32x2 utils
__device__ __forceinline__ void fma2(ull& a, ull x, ull b) {
    asm("fma.rn.f32x2 %0, %1, %2, %0;" : "+l"(a) : "l"(x), "l"(b));
}
__device__ __forceinline__ ull mul2(ull x, ull y) {
    ull r; asm("mul.rn.f32x2 %0, %1, %2;" : "=l"(r) : "l"(x), "l"(y)); return r;
}
__device__ __forceinline__ ull add2(ull x, ull y) {
    ull r; asm("add.rn.f32x2 %0, %1, %2;" : "=l"(r) : "l"(x), "l"(y)); return r;
}
__device__ __forceinline__ ull dup2(float x) {
    ull r; asm("mov.b64 %0, {%1, %1};" : "=l"(r) : "f"(x)); return r;
}
__device__ __forceinline__ float2 unp2(ull v) {
    float2 r; asm("mov.b64 {%0, %1}, %2;" : "=f"(r.x), "=f"(r.y) : "l"(v));
    return r;
}

// ------------------------------------------------------------- cp.async utils
__device__ __forceinline__ void cp16(void* smem_dst, const void* gmem_src) {
    const uint s = (uint)__cvta_generic_to_shared(smem_dst);
    asm volatile("cp.async.cg.shared.global [%0], [%1], 16;"
                 :: "r"(s), "l"(gmem_src) : "memory");
}
__device__ __forceinline__ void cp_commit() {
    asm volatile("cp.async.commit_group;" ::: "memory");
}
template <int N>
__device__ __forceinline__ void cp_wait() {
    asm volatile("cp.async.wait_group %0;" :: "n"(N) : "memory");
}

// ----------------------------------------------------------------- CSR build
__global__ void __launch_bounds__(256) hist_kernel(const int* __restrict__ dst) {
    for (long long e = (long long)blockIdx.x * 256 + threadIdx.x; e < EE;
         e += (long long)gridDim.x * 256)
        atomicAdd(&g_deg[dst[e]], 1);
}

// single-pass scan with aggregate lookback (98 blocks, all co-resident)
__global__ void __launch_bounds__(256) scan_kernel() {
    __shared__ int s[256];
    __shared__ int pre;
    const int b = blockIdx.x, t = threadIdx.x;

    int v[4];
    #pragma unroll
    for (int j = 0; j < 4; j++) {
        int i = b * 1024 + t * 4 + j;
        v[j] = (i < NND) ? g_deg[i] : 0;
    }
    const int tot = v[0] + v[1] + v[2] + v[3];
    s[t] = tot; __syncthreads();
    for (int off = 1; off < 256; off <<= 1) {
        int x = (t >= off) ? s[t - off] : 0;
        __syncthreads();
        s[t] += x;
        __syncthreads();
    }
    // publish this chunk's aggregate
    if (t == 255)
        atomicExch(&g_partial[b], (1ull << 32) | (uint)s[255]);

    // gather predecessors' aggregates in parallel (t < b spins on pred t)
    __shared__ int predsum[128];
    if (t < 128) predsum[t] = 0;
    __syncthreads();
    if (t < b) {
        ull p;
        do { p = atomicAdd(&g_partial[t], 0ull); } while (!(p >> 32));
        predsum[t] = (int)(uint)p;
    }
    __syncthreads();
    if (t == 0) {
        int acc = 0;
        for (int i = 0; i < b; i++) acc += predsum[i];
        pre = acc;
    }
    __syncthreads();

    int run = pre + s[t] - tot;       // exclusive prefix for this thread's elem 0
    #pragma unroll
    for (int j = 0; j < 4; j++) {
        int i = b * 1024 + t * 4 + j;
        if (i < NND) { g_rowptr[i] = run; g_cur[i] = run; }
        run += v[j];
    }
    if (b == 0 && t == 0) g_rowptr[NND] = EE;
}

__global__ void __launch_bounds__(256) csr_scatter_kernel(
    const int* __restrict__ src, const int* __restrict__ dst,
    const int* __restrict__ ety, const float* __restrict__ norm)
{
    for (long long e = (long long)blockIdx.x * 256 + threadIdx.x; e < EE;
         e += (long long)gridDim.x * 256) {
        const int d = dst[e];
        const int pos = atomicAdd(&g_cur[d], 1);
        const ull v = ((ull)__float_as_uint(norm[e]) << 32)
                    | (uint)(src[e] | (ety[e] << 20));
        g_edata[pos] = v;
    }
}

// ----------------------------------------------------------------------------
// Fused RGCN layer. 256 threads, 64 dst nodes, 2 blocks/SM.
//  phase 1: aggB[d,b,:] = sum_{e->d} wcomp[ety,b]*norm * X[src]   (-> smem)
//           dynamic row grab; TWO edges in flight per warp (half-warp x float4)
//  phase 2: out[d,:] = sum_b bases_b^T aggB[d,b,:]
//           bases staged per-basis (16KB panels) via double-buffered cp.async
// ----------------------------------------------------------------------------
__global__ void __launch_bounds__(LBLK, 2) layer_kernel(
    const float* __restrict__ Xin, const float* __restrict__ bases,
    const float* __restrict__ wcomp, const int* __restrict__ rowptr,
    const ull* __restrict__ edata, float* __restrict__ Out, int relu_out)
{
    extern __shared__ float sm[];
    float* buf0 = sm;                         // 4096 floats (one base panel)
    float* buf1 = sm + 4096;                  // 4096 floats
    float* aggs = sm + 8192;                  // 64 * 256 floats
    ull*   wc2  = (ull*)(sm + 8192 + 16384);  // 32 ull (wcomp dup'd to f32x2)
    __shared__ int rowctr;

    const int tid = threadIdx.x;
    const int n0 = blockIdx.x * NODES_PB;

    if (tid < RR * BB) wc2[tid] = dup2(wcomp[tid]);
    if (tid == 0) rowctr = 0;

    // prefetch base panels 0 and 1 (16KB each) behind phase 1
    #pragma unroll
    for (int j = 0; j < 4; j++)
        cp16(buf0 + (tid + j * LBLK) * 4, bases + 0 * DD * DD + (tid + j * LBLK) * 4);
    cp_commit();
    #pragma unroll
    for (int j = 0; j < 4; j++)
        cp16(buf1 + (tid + j * LBLK) * 4, bases + 1 * DD * DD + (tid + j * LBLK) * 4);
    cp_commit();

    __syncthreads();   // wc2 + rowctr visible

    // ---- phase 1: half-warp per edge, float4 lanes, 2 edges in flight ----
    const int lane = tid & 31;
    const int half = lane >> 4;               // 0 or 1
    const int ol   = (lane & 15) * 4;         // float4 offset within row

    while (true) {
        int k;
        if (lane == 0) k = atomicAdd(&rowctr, 1);
        k = __shfl_sync(0xffffffffu, k, 0);
        if (k >= NODES_PB) break;
        const int d = n0 + k;
        if (d >= NND) continue;

        const int beg = rowptr[d];
        const int end = rowptr[d + 1];

        ull a[BB][2];
        #pragma unroll
        for (int b = 0; b < BB; b++) { a[b][0] = 0; a[b][1] = 0; }

        // batches of 8 edges: this half handles e0 + 2j + half, j=0..3
        for (int e0 = beg; e0 < end; e0 += 8) {
            ull ed[4];
            #pragma unroll
            for (int j = 0; j < 4; j++) {
                int idx = e0 + 2 * j + half;
                if (idx > end - 1) idx = end - 1;
                ed[j] = __ldg(edata + idx);
            }
            float4 xv[4];
            #pragma unroll
            for (int j = 0; j < 4; j++) {
                const int s = (uint)ed[j] & 0xFFFFF;
                xv[j] = *(const float4*)(Xin + (size_t)s * DD + ol);
            }
            #pragma unroll
            for (int j = 0; j < 4; j++) {
                float nm = __uint_as_float((uint)(ed[j] >> 32));
                if (e0 + 2 * j + half >= end) nm = 0.f;     // predicated tail
                const int r = ((uint)ed[j] >> 20) & 7;
                const ull nm2 = dup2(nm);
                const ull* xp = (const ull*)&xv[j];
                const ull x0 = mul2(xp[0], nm2);
                const ull x1 = mul2(xp[1], nm2);
                const ulonglong2 wA = *(const ulonglong2*)&wc2[r * 4 + 0];
                const ulonglong2 wB = *(const ulonglong2*)&wc2[r * 4 + 2];
                fma2(a[0][0], wA.x, x0); fma2(a[0][1], wA.x, x1);
                fma2(a[1][0], wA.y, x0); fma2(a[1][1], wA.y, x1);
                fma2(a[2][0], wB.x, x0); fma2(a[2][1], wB.x, x1);
                fma2(a[3][0], wB.y, x0); fma2(a[3][1], wB.y, x1);
            }
        }

        // reduce the two half-warps, then lanes 0-15 store float4s
        #pragma unroll
        for (int b = 0; b < BB; b++) {
            a[b][0] = add2(a[b][0], __shfl_xor_sync(0xffffffffu, a[b][0], 16));
            a[b][1] = add2(a[b][1], __shfl_xor_sync(0xffffffffu, a[b][1], 16));
        }
        if (lane < 16) {
            #pragma unroll
            for (int b = 0; b < BB; b++) {
                ull* ag = (ull*)(aggs + k * (BB * DD) + b * DD + ol);
                ag[0] = a[b][0];
                ag[1] = a[b][1];
            }
        }
    }

    // ---- phase 2 ----
    const int o4 = (tid & 15) * 4;            // output quad
    const int q  = tid >> 4;                  // 0..15, 4 nodes each

    ull acc[4][2];
    #pragma unroll
    for (int n = 0; n < 4; n++) { acc[n][0] = 0; acc[n][1] = 0; }

    #pragma unroll
    for (int b = 0; b < BB; b++) {
        if (b < BB - 1) cp_wait<1>(); else cp_wait<0>();
        __syncthreads();                      // panel b ready + aggs visible

        const float* bb = (b & 1) ? buf1 : buf0;
        const float* ab = aggs + q * 4 * (BB * DD) + b * DD;

        #pragma unroll 4
        for (int i = 0; i < DD; i++) {
            const float4 bv = *(const float4*)(bb + i * DD + o4);
            const ull* bp = (const ull*)&bv;
            #pragma unroll
            for (int n = 0; n < 4; n++) {
                const ull x2 = dup2(ab[n * (BB * DD) + i]);
                fma2(acc[n][0], x2, bp[0]);
                fma2(acc[n][1], x2, bp[1]);
            }
        }
        __syncthreads();                      // done reading panel b
        if (b + 2 < BB) {
            float* dstb = (b & 1) ? buf1 : buf0;
            #pragma unroll
            for (int j = 0; j < 4; j++)
                cp16(dstb + (tid + j * LBLK) * 4,
                     bases + (b + 2) * DD * DD + (tid + j * LBLK) * 4);
            cp_commit();
        }
    }

    #pragma unroll
    for (int n = 0; n < 4; n++) {
        const int node = n0 + q * 4 + n;
        if (node >= NND) continue;
        const float2 lo = unp2(acc[n][0]);
        const float2 hi = unp2(acc[n][1]);
        float4 o;
        if (relu_out) {
            o.x = fmaxf(lo.x, 0.f); o.y = fmaxf(lo.y, 0.f);
            o.z = fmaxf(hi.x, 0.f); o.w = fmaxf(hi.y, 0.f);
        } else {
            o.x = lo.x; o.y = lo.y; o.z = hi.x; o.w = hi.y;
        }
        *(float4*)(Out + (size_t)node * DD + o4) = o;
    }
}

// ----------------------------------------------------------------------------
// Decoder: rec[n] = (relu(henc[n] @ W1 + b1)) @ W2 + b2.  One warp per node.
// ----------------------------------------------------------------------------
__global__ void __launch_bounds__(256) decoder_kernel(
    const float* __restrict__ henc, const float* __restrict__ w1,
    const float* __restrict__ b1, const float* __restrict__ w2,
    const float* __restrict__ b2, float* __restrict__ rec)
{
    __shared__ float w1s[DD * DD];
    __shared__ float w2s[DD], b1s[DD];
    __shared__ float b2s;
    const int tid = threadIdx.x;
    for (int i = tid; i < DD * DD; i += 256) w1s[i] = w1[i];
    if (tid < DD) { w2s[tid] = w2[tid]; b1s[tid] = b1[tid]; }
    if (tid == 0) b2s = b2[0];
    __syncthreads();

    const int lane = tid & 31;
    const int w = tid >> 5;
    for (int node = blockIdx.x * 8 + w; node < NND; node += gridDim.x * 8) {
        const float xa = henc[(size_t)node * DD + lane];
        const float xb = henc[(size_t)node * DD + 32 + lane];
        float s0 = b1s[lane], s1 = b1s[lane + 32];
        #pragma unroll
        for (int i = 0; i < 32; i++) {
            const float xi = __shfl_sync(0xffffffffu, xa, i);
            s0 += xi * w1s[i * DD + lane];
            s1 += xi * w1s[i * DD + lane + 32];
        }
        #pragma unroll
        for (int i = 0; i < 32; i++) {
            const float xi = __shfl_sync(0xffffffffu, xb, i);
            s0 += xi * w1s[(32 + i) * DD + lane];
            s1 += xi * w1s[(32 + i) * DD + lane + 32];
        }
        s0 = fmaxf(s0, 0.f); s1 = fmaxf(s1, 0.f);
        float v = s0 * w2s[lane] + s1 * w2s[lane + 32];
        #pragma unroll
        for (int off = 16; off; off >>= 1)
            v += __shfl_down_sync(0xffffffffu, v, off);
        if (lane == 0) rec[node] = v + b2s;
    }
}

// ----------------------------------------------------------------------------
extern "C" void kernel_launch(void* const* d_in, const int* in_sizes, int n_in,
                              void* d_out, int out_size)
{
    const float* h      = (const float*)d_in[0];
    const int*   src    = (const int*)  d_in[1];
    const int*   dst    = (const int*)  d_in[2];
    const int*   ety    = (const int*)  d_in[3];
    const float* norm   = (const float*)d_in[4];
    const float* bases0 = (const float*)d_in[5];
    const float* wcomp0 = (const float*)d_in[6];
    const float* bases1 = (const float*)d_in[7];
    const float* wcomp1 = (const float*)d_in[8];
    const float* bases2 = (const float*)d_in[9];
    const float* wcomp2 = (const float*)d_in[10];
    const float* dw1    = (const float*)d_in[11];
    const float* db1    = (const float*)d_in[12];
    const float* dw2    = (const float*)d_in[13];
    const float* db2    = (const float*)d_in[14];

    float* out  = (float*)d_out;
    float* rec  = out;                 // [N]
    float* henc = out + NND;           // [N, D]

    float *h1, *h2;
    int *deg, *rowptr;
    ull *edata, *partial;
    cudaGetSymbolAddress((void**)&h1, g_h1);
    cudaGetSymbolAddress((void**)&h2, g_h2);
    cudaGetSymbolAddress((void**)&deg, g_deg);
    cudaGetSymbolAddress((void**)&rowptr, g_rowptr);
    cudaGetSymbolAddress((void**)&edata, g_edata);
    cudaGetSymbolAddress((void**)&partial, g_partial);

    const int SMEM_L = (2 * DD * DD + NODES_PB * BB * DD + 64) * (int)sizeof(float);
    cudaFuncSetAttribute(layer_kernel,
                         cudaFuncAttributeMaxDynamicSharedMemorySize, SMEM_L);

    // ---- CSR by dst (once, reused 3x) ----
    cudaMemsetAsync(deg, 0, NND * sizeof(int));
    cudaMemsetAsync(partial, 0, NCH * sizeof(ull));
    hist_kernel<<<1024, 256>>>(dst);                     // launch 1
    scan_kernel<<<NCH, 256>>>();                         // launch 2
    csr_scatter_kernel<<<1024, 256>>>(src, dst, ety, norm); // launch 3

    // ---- 3 fused RGCN layers (launch 4 gets profiled) ----
    layer_kernel<<<NLB, LBLK, SMEM_L>>>(h,  bases0, wcomp0, rowptr, edata, h1, 1);
    layer_kernel<<<NLB, LBLK, SMEM_L>>>(h1, bases1, wcomp1, rowptr, edata, h2, 1);
    layer_kernel<<<NLB, LBLK, SMEM_L>>>(h2, bases2, wcomp2, rowptr, edata, henc, 0);

    // ---- decoder ----
    decoder_kernel<<<2048, 256>>>(henc, dw1, db1, dw2, db2, rec);
}

// round 10
// speedup vs baseline: 1.5156x; 1.5156x over previous
#include <cuda_runtime.h>
#include <cstddef>
#include <cstdint>

#define NND 100000
#define EE  1600000
#define RR  8
#define BB  4
#define DD  64

#define LBLK 256                 // threads per layer block
#define NODES_PB 48              // dst nodes per layer block
#define NLB ((NND + NODES_PB - 1) / NODES_PB)   // 2084
#define NCH ((NND + 1023) / 1024)               // 98 scan chunks

typedef unsigned long long ull;
typedef unsigned int uint;

// Scratch (no runtime allocation allowed) ------------------------------------
__device__ float g_h1[(size_t)NND * DD];
__device__ float g_h2[(size_t)NND * DD];
__device__ int   g_deg[NND];
__device__ int   g_rowptr[NND + 1];
__device__ int   g_cur[NND];
__device__ ull   g_partial[NCH];  // lookback: (ready<<32)|chunk_sum
__device__ ull   g_edata[EE];     // (norm bits << 32) | (ety << 20) | src

// ---------------------------------------------------------------- f32x2 utils
__device__ __forceinline__ void fma2(ull& a, ull x, ull b) {
    asm("fma.rn.f32x2 %0, %1, %2, %0;" : "+l"(a) : "l"(x), "l"(b));
}
__device__ __forceinline__ ull mul2(ull x, ull y) {
    ull r; asm("mul.rn.f32x2 %0, %1, %2;" : "=l"(r) : "l"(x), "l"(y)); return r;
}
__device__ __forceinline__ ull dup2(float x) {
    ull r; asm("mov.b64 %0, {%1, %1};" : "=l"(r) : "f"(x)); return r;
}
__device__ __forceinline__ float2 unp2(ull v) {
    float2 r; asm("mov.b64 {%0, %1}, %2;" : "=f"(r.x), "=f"(r.y) : "l"(v));
    return r;
}

// ------------------------------------------------------------- cp.async utils
__device__ __forceinline__ void cp16(void* smem_dst, const void* gmem_src) {
    const uint s = (uint)__cvta_generic_to_shared(smem_dst);
    asm volatile("cp.async.cg.shared.global [%0], [%1], 16;"
                 :: "r"(s), "l"(gmem_src) : "memory");
}
__device__ __forceinline__ void cp_commit() {
    asm volatile("cp.async.commit_group;" ::: "memory");
}
template <int N>
__device__ __forceinline__ void cp_wait() {
    asm volatile("cp.async.wait_group %0;" :: "n"(N) : "memory");
}

// ----------------------------------------------------------------- CSR build
__global__ void __launch_bounds__(256) hist_kernel(const int* __restrict__ dst) {
    for (long long e = (long long)blockIdx.x * 256 + threadIdx.x; e < EE;
         e += (long long)gridDim.x * 256)
        atomicAdd(&g_deg[dst[e]], 1);
}

// single-pass scan with aggregate lookback (98 blocks, all co-resident)
__global__ void __launch_bounds__(256) scan_kernel() {
    __shared__ int s[256];
    __shared__ int pre;
    const int b = blockIdx.x, t = threadIdx.x;

    int v[4];
    #pragma unroll
    for (int j = 0; j < 4; j++) {
        int i = b * 1024 + t * 4 + j;
        v[j] = (i < NND) ? g_deg[i] : 0;
    }
    const int tot = v[0] + v[1] + v[2] + v[3];
    s[t] = tot; __syncthreads();
    for (int off = 1; off < 256; off <<= 1) {
        int x = (t >= off) ? s[t - off] : 0;
        __syncthreads();
        s[t] += x;
        __syncthreads();
    }
    if (t == 255)
        atomicExch(&g_partial[b], (1ull << 32) | (uint)s[255]);

    __shared__ int predsum[128];
    if (t < 128) predsum[t] = 0;
    __syncthreads();
    if (t < b) {
        ull p;
        do { p = atomicAdd(&g_partial[t], 0ull); } while (!(p >> 32));
        predsum[t] = (int)(uint)p;
    }
    __syncthreads();
    if (t == 0) {
        int acc = 0;
        for (int i = 0; i < b; i++) acc += predsum[i];
        pre = acc;
    }
    __syncthreads();

    int run = pre + s[t] - tot;
    #pragma unroll
    for (int j = 0; j < 4; j++) {
        int i = b * 1024 + t * 4 + j;
        if (i < NND) { g_rowptr[i] = run; g_cur[i] = run; }
        run += v[j];
    }
    if (b == 0 && t == 0) g_rowptr[NND] = EE;
}

__global__ void __launch_bounds__(256) csr_scatter_kernel(
    const int* __restrict__ src, const int* __restrict__ dst,
    const int* __restrict__ ety, const float* __restrict__ norm)
{
    for (long long e = (long long)blockIdx.x * 256 + threadIdx.x; e < EE;
         e += (long long)gridDim.x * 256) {
        const int d = dst[e];
        const int pos = atomicAdd(&g_cur[d], 1);
        const ull v = ((ull)__float_as_uint(norm[e]) << 32)
                    | (uint)(src[e] | (ety[e] << 20));
        g_edata[pos] = v;
    }
}

// ----------------------------------------------------------------------------
// Fused RGCN layer. 256 threads, 48 dst nodes, 3 blocks/SM (24 warps = 37.5%).
//  phase 1: aggB[d,b,:] = sum_{e->d} wcomp[ety,b]*norm * X[src]   (-> smem)
//           full warp x float2 per edge, 8 edges in flight (round-7 scheme)
//  phase 2: out[d,:] = sum_b bases_b^T aggB[d,b,:]
//           single 16KB bases panel, reloaded per basis via cp.async
// smem: 4096 (panel) + 12288 (agg) + 64 (wc2) floats = 65.8 KB
// ----------------------------------------------------------------------------
__global__ void __launch_bounds__(LBLK, 3) layer_kernel(
    const float* __restrict__ Xin, const float* __restrict__ bases,
    const float* __restrict__ wcomp, const int* __restrict__ rowptr,
    const ull* __restrict__ edata, float* __restrict__ Out, int relu_out)
{
    extern __shared__ float sm[];
    float* buf  = sm;                          // 4096 floats (one base panel)
    float* aggs = sm + 4096;                   // 48 * 256 floats
    ull*   wc2  = (ull*)(sm + 4096 + NODES_PB * BB * DD);  // 32 ull
    __shared__ int rowctr;

    const int tid = threadIdx.x;
    const int n0 = blockIdx.x * NODES_PB;

    if (tid < RR * BB) wc2[tid] = dup2(wcomp[tid]);
    if (tid == 0) rowctr = 0;

    // prefetch base panel 0 behind phase 1
    #pragma unroll
    for (int j = 0; j < 4; j++)
        cp16(buf + (tid + j * LBLK) * 4, bases + (tid + j * LBLK) * 4);
    cp_commit();

    __syncthreads();   // wc2 + rowctr visible

    // ---- phase 1: full warp per edge (float2 lanes), 8 edges in flight ----
    const int lane = tid & 31;
    while (true) {
        int k;
        if (lane == 0) k = atomicAdd(&rowctr, 1);
        k = __shfl_sync(0xffffffffu, k, 0);
        if (k >= NODES_PB) break;
        const int d = n0 + k;
        if (d >= NND) continue;

        const int beg = rowptr[d];
        const int end = rowptr[d + 1];

        ull a0 = 0, a1 = 0, a2 = 0, a3 = 0;
        for (int e = beg; e < end; e += 8) {
            ull ed[8];
            #pragma unroll
            for (int j = 0; j < 8; j++) {
                const int idx = (e + j < end) ? e + j : end - 1;
                ed[j] = __ldg(edata + idx);
            }
            ull xv[8];
            #pragma unroll
            for (int j = 0; j < 8; j++) {
                const int s = (uint)ed[j] & 0xFFFFF;
                xv[j] = *(const ull*)(Xin + (size_t)s * DD + 2 * lane);
            }
            #pragma unroll
            for (int j = 0; j < 8; j++) {
                float nm = __uint_as_float((uint)(ed[j] >> 32));
                if (e + j >= end) nm = 0.f;        // predicated tail
                const int r = ((uint)ed[j] >> 20) & 7;
                const ull xnm = mul2(xv[j], dup2(nm));
                fma2(a0, wc2[r * 4 + 0], xnm);
                fma2(a1, wc2[r * 4 + 1], xnm);
                fma2(a2, wc2[r * 4 + 2], xnm);
                fma2(a3, wc2[r * 4 + 3], xnm);
            }
        }
        ull* ag = (ull*)(aggs + k * (BB * DD));
        ag[0 * 32 + lane] = a0;
        ag[1 * 32 + lane] = a1;
        ag[2 * 32 + lane] = a2;
        ag[3 * 32 + lane] = a3;
    }

    // ---- phase 2: 16 output quads x 16 node groups of 3 ----
    const int o4 = (tid & 15) * 4;            // output quad
    const int q  = tid >> 4;                  // 0..15, 3 nodes each

    ull acc[3][2];
    #pragma unroll
    for (int n = 0; n < 3; n++) { acc[n][0] = 0; acc[n][1] = 0; }

    #pragma unroll
    for (int b = 0; b < BB; b++) {
        cp_wait<0>();
        __syncthreads();                      // panel b ready + aggs visible

        const float* ab = aggs + q * 3 * (BB * DD) + b * DD;

        #pragma unroll 4
        for (int i = 0; i < DD; i++) {
            const float4 bv = *(const float4*)(buf + i * DD + o4);
            const ull* bp = (const ull*)&bv;
            #pragma unroll
            for (int n = 0; n < 3; n++) {
                const ull x2 = dup2(ab[n * (BB * DD) + i]);
                fma2(acc[n][0], x2, bp[0]);
                fma2(acc[n][1], x2, bp[1]);
            }
        }
        __syncthreads();                      // done reading panel b
        if (b + 1 < BB) {
            #pragma unroll
            for (int j = 0; j < 4; j++)
                cp16(buf + (tid + j * LBLK) * 4,
                     bases + (b + 1) * DD * DD + (tid + j * LBLK) * 4);
            cp_commit();
        }
    }

    #pragma unroll
    for (int n = 0; n < 3; n++) {
        const int node = n0 + q * 3 + n;
        if (node >= NND) continue;
        const float2 lo = unp2(acc[n][0]);
        const float2 hi = unp2(acc[n][1]);
        float4 o;
        if (relu_out) {
            o.x = fmaxf(lo.x, 0.f); o.y = fmaxf(lo.y, 0.f);
            o.z = fmaxf(hi.x, 0.f); o.w = fmaxf(hi.y, 0.f);
        } else {
            o.x = lo.x; o.y = lo.y; o.z = hi.x; o.w = hi.y;
        }
        *(float4*)(Out + (size_t)node * DD + o4) = o;
    }
}

// ----------------------------------------------------------------------------
// Decoder: rec[n] = (relu(henc[n] @ W1 + b1)) @ W2 + b2.  One warp per node.
// ----------------------------------------------------------------------------
__global__ void __launch_bounds__(256) decoder_kernel(
    const float* __restrict__ henc, const float* __restrict__ w1,
    const float* __restrict__ b1, const float* __restrict__ w2,
    const float* __restrict__ b2, float* __restrict__ rec)
{
    __shared__ float w1s[DD * DD];
    __shared__ float w2s[DD], b1s[DD];
    __shared__ float b2s;
    const int tid = threadIdx.x;
    for (int i = tid; i < DD * DD; i += 256) w1s[i] = w1[i];
    if (tid < DD) { w2s[tid] = w2[tid]; b1s[tid] = b1[tid]; }
    if (tid == 0) b2s = b2[0];
    __syncthreads();

    const int lane = tid & 31;
    const int w = tid >> 5;
    for (int node = blockIdx.x * 8 + w; node < NND; node += gridDim.x * 8) {
        const float xa = henc[(size_t)node * DD + lane];
        const float xb = henc[(size_t)node * DD + 32 + lane];
        float s0 = b1s[lane], s1 = b1s[lane + 32];
        #pragma unroll
        for (int i = 0; i < 32; i++) {
            const float xi = __shfl_sync(0xffffffffu, xa, i);
            s0 += xi * w1s[i * DD + lane];
            s1 += xi * w1s[i * DD + lane + 32];
        }
        #pragma unroll
        for (int i = 0; i < 32; i++) {
            const float xi = __shfl_sync(0xffffffffu, xb, i);
            s0 += xi * w1s[(32 + i) * DD + lane];
            s1 += xi * w1s[(32 + i) * DD + lane + 32];
        }
        s0 = fmaxf(s0, 0.f); s1 = fmaxf(s1, 0.f);
        float v = s0 * w2s[lane] + s1 * w2s[lane + 32];
        #pragma unroll
        for (int off = 16; off; off >>= 1)
            v += __shfl_down_sync(0xffffffffu, v, off);
        if (lane == 0) rec[node] = v + b2s;
    }
}

// ----------------------------------------------------------------------------
extern "C" void kernel_launch(void* const* d_in, const int* in_sizes, int n_in,
                              void* d_out, int out_size)
{
    const float* h      = (const float*)d_in[0];
    const int*   src    = (const int*)  d_in[1];
    const int*   dst    = (const int*)  d_in[2];
    const int*   ety    = (const int*)  d_in[3];
    const float* norm   = (const float*)d_in[4];
    const float* bases0 = (const float*)d_in[5];
    const float* wcomp0 = (const float*)d_in[6];
    const float* bases1 = (const float*)d_in[7];
    const float* wcomp1 = (const float*)d_in[8];
    const float* bases2 = (const float*)d_in[9];
    const float* wcomp2 = (const float*)d_in[10];
    const float* dw1    = (const float*)d_in[11];
    const float* db1    = (const float*)d_in[12];
    const float* dw2    = (const float*)d_in[13];
    const float* db2    = (const float*)d_in[14];

    float* out  = (float*)d_out;
    float* rec  = out;                 // [N]
    float* henc = out + NND;           // [N, D]

    float *h1, *h2;
    int *deg, *rowptr;
    ull *edata, *partial;
    cudaGetSymbolAddress((void**)&h1, g_h1);
    cudaGetSymbolAddress((void**)&h2, g_h2);
    cudaGetSymbolAddress((void**)&deg, g_deg);
    cudaGetSymbolAddress((void**)&rowptr, g_rowptr);
    cudaGetSymbolAddress((void**)&edata, g_edata);
    cudaGetSymbolAddress((void**)&partial, g_partial);

    const int SMEM_L = (DD * DD + NODES_PB * BB * DD + 64) * (int)sizeof(float);
    cudaFuncSetAttribute(layer_kernel,
                         cudaFuncAttributeMaxDynamicSharedMemorySize, SMEM_L);

    // ---- CSR by dst (once, reused 3x) ----
    cudaMemsetAsync(deg, 0, NND * sizeof(int));
    cudaMemsetAsync(partial, 0, NCH * sizeof(ull));
    hist_kernel<<<1024, 256>>>(dst);                        // launch 1
    scan_kernel<<<NCH, 256>>>();                            // launch 2
    csr_scatter_kernel<<<1024, 256>>>(src, dst, ety, norm); // launch 3

    // ---- 3 fused RGCN layers (launch 4 gets profiled) ----
    layer_kernel<<<NLB, LBLK, SMEM_L>>>(h,  bases0, wcomp0, rowptr, edata, h1, 1);
    layer_kernel<<<NLB, LBLK, SMEM_L>>>(h1, bases1, wcomp1, rowptr, edata, h2, 1);
    layer_kernel<<<NLB, LBLK, SMEM_L>>>(h2, bases2, wcomp2, rowptr, edata, henc, 0);

    // ---- decoder ----
    decoder_kernel<<<2048, 256>>>(henc, dw1, db1, dw2, db2, rec);
}